// round 5
// baseline (speedup 1.0000x reference)
#include <cuda_runtime.h>

#define H     51
#define E     16
#define TPB   544
#define XCH   40
#define B_TOT 2048
#define HPAD  56            // padded state row (floats); floats 51..55 stay 0

typedef unsigned long long ull;

struct __align__(16) Smem {
    float PA[E][320];       // phase-A partials: rows 0..152 = w_hh1, 153..305 = w_hh2
    float PB[E][160];       // phase-B partials: rows 0..152 = w_ih2
    float h1b[E][HPAD];
    float h2b[E][HPAD];
    float xb[E][XCH];
    float wlins[HPAD];
    float wr1s[52], wz1s[52], wn1s[52];
    float bR1s[52], bZ1s[52], bIN1s[52], bHN1s[52];
    float bR2s[52], bZ2s[52], bIN2s[52], bHN2s[52];
    float outp[E];
    float blins;
};

__device__ __forceinline__ void fma2(ull& d, ull a, ull b) {
    asm("fma.rn.f32x2 %0, %1, %2, %0;" : "+l"(d) : "l"(a), "l"(b));
}
__device__ __forceinline__ ull pack2(float a, float b) {
    ull r; asm("mov.b64 %0, {%1,%2};" : "=l"(r) : "f"(a), "f"(b)); return r;
}
__device__ __forceinline__ float sum2(ull v) {
    float a, b; asm("mov.b64 {%0,%1}, %2;" : "=f"(a), "=f"(b) : "l"(v));
    return a + b;
}
__device__ __forceinline__ float sigmoid_(float v) {
    return __fdividef(1.0f, 1.0f + __expf(-v));
}
__device__ __forceinline__ float tanh_(float v) {
    return __fdividef(2.0f, 1.0f + __expf(-2.0f * v)) - 1.0f;
}
__device__ __forceinline__ float gru_cell(float gr, float gz, float gin,
                                          float ghn, float ho) {
    float r = sigmoid_(gr);
    float z = sigmoid_(gz);
    float n = tanh_(fmaf(r, ghn, gin));
    return fmaf(z, ho - n, n);
}
// 51-length dot: weights in regs (26 packed pairs, pair 25 = (w50, 0)),
// h from smem (broadcast across warp lanes).
__device__ __forceinline__ float dot51(const ull* w, const float* hvec) {
    const ulonglong2* hp = (const ulonglong2*)hvec;
    ull a0 = 0ull, a1 = 0ull;
    #pragma unroll
    for (int p = 0; p < 13; p++) {
        ulonglong2 hv = hp[p];
        fma2(a0, hv.x, w[2 * p]);
        fma2(a1, hv.y, w[2 * p + 1]);
    }
    ull s; asm("add.rn.f32x2 %0, %1, %2;" : "=l"(s) : "l"(a0), "l"(a1));
    return sum2(s);
}

__global__ void __launch_bounds__(TPB, 1) gru_stack_kernel(
    const float* __restrict__ x,
    const float* __restrict__ w_ih1, const float* __restrict__ w_hh1,
    const float* __restrict__ b_ih1, const float* __restrict__ b_hh1,
    const float* __restrict__ w_ih2, const float* __restrict__ w_hh2,
    const float* __restrict__ b_ih2, const float* __restrict__ b_hh2,
    const float* __restrict__ w_lin, const float* __restrict__ b_lin,
    float* __restrict__ out, int T, int F)
{
    __shared__ Smem s;
    const int tid  = threadIdx.x;
    const int base = blockIdx.x * E;
    const int TF   = T + F;

    // ---- role decode ----
    const bool isA   = (tid < 384);
    const bool isDup = (tid >= 306 && tid < 384);      // duplicate owners of w_hh1 rows 0..77
    const bool isB   = (tid >= 384 && tid < 537);
    const int  prow  = isA ? (isDup ? tid - 306 : tid) : 0;   // PA row index
    const bool useH2 = isA && !isDup && (prow >= 153);        // w_hh2 rows read h2
    const int  elA0  = isDup ? 8 : 0;
    const int  elA1  = isA ? (isDup ? 16 : ((prow < 78) ? 8 : 16)) : 0;
    const int  rowB  = tid - 384;
    const bool isOut = (tid >= 368 && tid < 384);      // dup lanes rows 62..77 (light)

    // ---- load this thread's weight row into registers ----
    ull w[26];
    {
        const float* src;
        if (isA) src = (prow < 153) ? (w_hh1 + prow * H)
                                    : (w_hh2 + (prow - 153) * H);
        else if (isB) src = w_ih2 + rowB * H;
        else src = w_hh1;   // idle threads: harmless row 0
        #pragma unroll
        for (int p = 0; p < 26; p++) {
            float f0 = src[2 * p];
            float f1 = (2 * p + 1 < H) ? src[2 * p + 1] : 0.f;
            w[p] = pack2(f0, f1);
        }
    }

    // ---- one-time smem init ----
    for (int i = tid; i < 52; i += TPB) {
        bool v = (i < H);
        s.wr1s[i] = v ? w_ih1[i] : 0.f;
        s.wz1s[i] = v ? w_ih1[H + i] : 0.f;
        s.wn1s[i] = v ? w_ih1[2 * H + i] : 0.f;
        s.bR1s[i]  = v ? (b_ih1[i] + b_hh1[i]) : 0.f;
        s.bZ1s[i]  = v ? (b_ih1[H + i] + b_hh1[H + i]) : 0.f;
        s.bIN1s[i] = v ? b_ih1[2 * H + i] : 0.f;
        s.bHN1s[i] = v ? b_hh1[2 * H + i] : 0.f;
        s.bR2s[i]  = v ? (b_ih2[i] + b_hh2[i]) : 0.f;
        s.bZ2s[i]  = v ? (b_ih2[H + i] + b_hh2[H + i]) : 0.f;
        s.bIN2s[i] = v ? b_ih2[2 * H + i] : 0.f;
        s.bHN2s[i] = v ? b_hh2[2 * H + i] : 0.f;
    }
    for (int i = tid; i < HPAD; i += TPB) s.wlins[i] = (i < H) ? w_lin[i] : 0.f;
    for (int i = tid; i < E * HPAD; i += TPB) {
        (&s.h1b[0][0])[i] = 0.f;
        (&s.h2b[0][0])[i] = 0.f;
    }
    for (int i = tid; i < E; i += TPB) s.outp[i] = 0.f;
    if (tid == 0) s.blins = b_lin[0];
    __syncthreads();

    for (int t = 0; t < TF; ++t) {
        // ---- stage x chunk (phase-1 only) ----
        if (t < T && (t % XCH) == 0) {
            for (int i = tid; i < E * XCH; i += TPB) {
                int e = i / XCH, c = i - e * XCH;
                int tg = t + c;
                s.xb[e][c] = (tg < T) ? x[(size_t)(base + e) * T + tg] : 0.f;
            }
            __syncthreads();
        }
        const int xidx = t % XCH;

        // ============ phase A: w_hh1 & w_hh2 dots (+ output of step t-1) ============
        if (isOut && t > 0) {
            int el = tid - 368;
            const ulonglong2* hp = (const ulonglong2*)s.h2b[el];
            const ulonglong2* wp = (const ulonglong2*)s.wlins;
            ull acc = pack2(s.blins, 0.f);
            #pragma unroll
            for (int p = 0; p < 13; p++) {
                ulonglong2 hv = hp[p], wv = wp[p];
                fma2(acc, hv.x, wv.x);
                fma2(acc, hv.y, wv.y);
            }
            float o = sum2(acc);
            out[(size_t)(base + el) * TF + (t - 1)] = o;
            s.outp[el] = o;
        }
        if (isA) {
            const float* hbase = useH2 ? &s.h2b[0][0] : &s.h1b[0][0];
            for (int el = elA0; el < elA1; ++el)
                s.PA[el][prow] = dot51(w, hbase + el * HPAD);
        }
        __syncthreads();

        // ============ ACT1: layer-1 gates -> h1 (in place) ============
        for (int task = tid; task < E * H; task += TPB) {
            int el = task / H, j = task - el * H;
            float xv = (t < T) ? s.xb[el][xidx] : s.outp[el];
            float gr  = s.PA[el][j]        + fmaf(xv, s.wr1s[j], s.bR1s[j]);
            float gz  = s.PA[el][H + j]    + fmaf(xv, s.wz1s[j], s.bZ1s[j]);
            float gin = fmaf(xv, s.wn1s[j], s.bIN1s[j]);
            float ghn = s.PA[el][2 * H + j] + s.bHN1s[j];
            s.h1b[el][j] = gru_cell(gr, gz, gin, ghn, s.h1b[el][j]);
        }
        __syncthreads();

        // ============ phase B: w_ih2 dots vs new h1 ============
        if (isB) {
            for (int el = 0; el < E; ++el)
                s.PB[el][rowB] = dot51(w, &s.h1b[el][0]);
        }
        __syncthreads();

        // ============ ACT2: layer-2 gates -> h2 (in place) ============
        for (int task = tid; task < E * H; task += TPB) {
            int el = task / H, j = task - el * H;
            float gr  = s.PA[el][153 + j]     + s.PB[el][j]     + s.bR2s[j];
            float gz  = s.PA[el][153 + H + j] + s.PB[el][H + j] + s.bZ2s[j];
            float gin = s.PB[el][2 * H + j] + s.bIN2s[j];
            float ghn = s.PA[el][153 + 2 * H + j] + s.bHN2s[j];
            s.h2b[el][j] = gru_cell(gr, gz, gin, ghn, s.h2b[el][j]);
        }
        __syncthreads();
    }

    // final output (step TF-1)
    if (tid < E) {
        const ulonglong2* hp = (const ulonglong2*)s.h2b[tid];
        const ulonglong2* wp = (const ulonglong2*)s.wlins;
        ull acc = pack2(s.blins, 0.f);
        #pragma unroll
        for (int p = 0; p < 13; p++) {
            ulonglong2 hv = hp[p], wv = wp[p];
            fma2(acc, hv.x, wv.x);
            fma2(acc, hv.y, wv.y);
        }
        out[(size_t)(base + tid) * TF + (TF - 1)] = sum2(acc);
    }
}

extern "C" void kernel_launch(void* const* d_in, const int* in_sizes, int n_in,
                              void* d_out, int out_size)
{
    const float* x     = (const float*)d_in[0];
    const float* w_ih1 = (const float*)d_in[1];
    const float* w_hh1 = (const float*)d_in[2];
    const float* b_ih1 = (const float*)d_in[3];
    const float* b_hh1 = (const float*)d_in[4];
    const float* w_ih2 = (const float*)d_in[5];
    const float* w_hh2 = (const float*)d_in[6];
    const float* b_ih2 = (const float*)d_in[7];
    const float* b_hh2 = (const float*)d_in[8];
    const float* w_lin = (const float*)d_in[9];
    const float* b_lin = (const float*)d_in[10];

    const int B  = B_TOT;
    const int T  = in_sizes[0] / B;
    const int TF = out_size / B;
    const int F  = TF - T;

    gru_stack_kernel<<<B / E, TPB>>>(
        x, w_ih1, w_hh1, b_ih1, b_hh1,
        w_ih2, w_hh2, b_ih2, b_hh2,
        w_lin, b_lin, (float*)d_out, T, F);
}

// round 6
// speedup vs baseline: 1.3461x; 1.3461x over previous
#include <cuda_runtime.h>

#define B_TOT 2048
#define H     51
#define HP    52           // padded gate rows (row 51 = zeros)
#define KP    56           // padded k stride per row (floats)
#define KU2   14           // KP in ulonglong2 units
#define PAIR  120          // floats per j-row-pair (2*56 + 8 pad)
#define NJG   26           // j-row-pair groups (covers 52 rows)
#define WSZ   (NJG*PAIR)   // floats per padded gate matrix = 3120
#define E     16           // elements per block
#define TPB   224          // 26 jg * 4 eg * 2 kh = 208 active (+16 clones)
#define XCH   40

typedef unsigned long long ull;

struct __align__(16) Smem {
    // padded gate matrices: row j at (j>>1)*PAIR + (j&1)*KP
    float l1r[WSZ], l1z[WSZ], l1n[WSZ];      // w_hh1
    float ir2[WSZ], iz2[WSZ], in2[WSZ];      // w_ih2
    float hr2[WSZ], hz2[WSZ], hn2[WSZ];      // w_hh2
    float wih1r[HP], wih1z[HP], wih1n[HP];   // w_ih1 columns (input dim 1)
    float bR1[HP], bZ1[HP], bIN1[HP], bHN1[HP];
    float bR2[HP], bZ2[HP], bIN2[HP], bHN2[HP];
    float wlin[KP];
    float h1[2][E][KP];                      // ping-pong, pads stay 0
    float h2[2][E][KP];
    float xbuf[E][XCH];
    float outp[E];
    float blin;
};

__device__ __forceinline__ void fma2(ull& d, ull a, ull b) {
    asm("fma.rn.f32x2 %0, %1, %2, %0;" : "+l"(d) : "l"(a), "l"(b));
}
__device__ __forceinline__ ull pack2(float a, float b) {
    ull r; asm("mov.b64 %0, {%1,%2};" : "=l"(r) : "f"(a), "f"(b)); return r;
}
__device__ __forceinline__ float sum2(ull v) {
    float a, b; asm("mov.b64 {%0,%1}, %2;" : "=f"(a), "=f"(b) : "l"(v));
    return a + b;
}
__device__ __forceinline__ float sigmoid_(float v) {
    return __fdividef(1.0f, 1.0f + __expf(-v));
}
__device__ __forceinline__ float tanh_(float v) {
    return __fdividef(2.0f, 1.0f + __expf(-2.0f * v)) - 1.0f;
}
__device__ __forceinline__ float gru_cell(float gr, float gz, float gin,
                                          float ghn, float ho) {
    float r = sigmoid_(gr);
    float z = sigmoid_(gz);
    float n = tanh_(fmaf(r, ghn, gin));
    return fmaf(z, ho - n, n);
}
// lane kh keeps jj=kh partial, receives partner's jj=kh partial (1 float shfl)
__device__ __forceinline__ float xred(ull a0, ull a1, int kh) {
    ull keep = kh ? a1 : a0;
    ull send = kh ? a0 : a1;
    float sf = sum2(send);
    return sum2(keep) + __shfl_xor_sync(0xFFFFFFFFu, sf, 1);
}

// fill one padded gate matrix (gate g of a [153][51] row-major source)
__device__ __forceinline__ void fill_mat(float* dst, const float* src, int g, int tid) {
    for (int idx = tid; idx < WSZ; idx += TPB) {
        int jg = idx / PAIR, rem = idx - jg * PAIR;
        int jj = rem / KP;                  // 0,1, or 2 => inter-pair pad
        int k  = rem - jj * KP;
        float v = 0.f;
        if (jj < 2) {
            int j = jg * 2 + jj;
            if (j < H && k < H) v = src[(g * H + j) * H + k];
        }
        dst[idx] = v;
    }
}

__global__ void __launch_bounds__(TPB, 1) gru_stack_kernel(
    const float* __restrict__ x,
    const float* __restrict__ w_ih1, const float* __restrict__ w_hh1,
    const float* __restrict__ b_ih1, const float* __restrict__ b_hh1,
    const float* __restrict__ w_ih2, const float* __restrict__ w_hh2,
    const float* __restrict__ b_ih2, const float* __restrict__ b_hh2,
    const float* __restrict__ w_lin, const float* __restrict__ b_lin,
    float* __restrict__ out, int T, int F)
{
    extern __shared__ float smem_f[];
    Smem* s = reinterpret_cast<Smem*>(smem_f);

    const int tid = threadIdx.x;
    const int kh  = tid & 1;                 // k-half, also owned jj
    const int eg  = (tid >> 1) & 3;          // element group: el = eg + 4*ei
    int jgt = tid >> 3; if (jgt > NJG - 1) jgt = NJG - 1;   // clone tail threads
    const int jg  = jgt;
    const int j0  = 2 * jg;
    const int jme = j0 + kh;                 // the gate row this lane finalizes
    const int kb  = kh * (KU2 / 2);          // k-half offset in u2 units (7)
    const int base = blockIdx.x * E;
    const int TF   = T + F;

    // ---------------- one-time init ----------------
    fill_mat(s->l1r, w_hh1, 0, tid); fill_mat(s->l1z, w_hh1, 1, tid); fill_mat(s->l1n, w_hh1, 2, tid);
    fill_mat(s->ir2, w_ih2, 0, tid); fill_mat(s->iz2, w_ih2, 1, tid); fill_mat(s->in2, w_ih2, 2, tid);
    fill_mat(s->hr2, w_hh2, 0, tid); fill_mat(s->hz2, w_hh2, 1, tid); fill_mat(s->hn2, w_hh2, 2, tid);
    for (int i = tid; i < HP; i += TPB) {
        bool v = (i < H);
        s->wih1r[i] = v ? w_ih1[i] : 0.f;
        s->wih1z[i] = v ? w_ih1[H + i] : 0.f;
        s->wih1n[i] = v ? w_ih1[2 * H + i] : 0.f;
        s->bR1[i]  = v ? (b_ih1[i] + b_hh1[i]) : 0.f;
        s->bZ1[i]  = v ? (b_ih1[H + i] + b_hh1[H + i]) : 0.f;
        s->bIN1[i] = v ? b_ih1[2 * H + i] : 0.f;
        s->bHN1[i] = v ? b_hh1[2 * H + i] : 0.f;
        s->bR2[i]  = v ? (b_ih2[i] + b_hh2[i]) : 0.f;
        s->bZ2[i]  = v ? (b_ih2[H + i] + b_hh2[H + i]) : 0.f;
        s->bIN2[i] = v ? b_ih2[2 * H + i] : 0.f;
        s->bHN2[i] = v ? b_hh2[2 * H + i] : 0.f;
    }
    for (int i = tid; i < KP; i += TPB) s->wlin[i] = (i < H) ? w_lin[i] : 0.f;
    if (tid == 0) s->blin = b_lin[0];
    {
        float* h1f = &s->h1[0][0][0];
        float* h2f = &s->h2[0][0][0];
        for (int i = tid; i < 2 * E * KP; i += TPB) { h1f[i] = 0.f; h2f[i] = 0.f; }
        for (int i = tid; i < E; i += TPB) s->outp[i] = 0.f;
    }
    __syncthreads();

    int cur = 0;
    for (int t = 0; t < TF; ++t) {
        if (t < T && (t % XCH) == 0) {
            for (int i = tid; i < E * XCH; i += TPB) {
                int e = i / XCH, c = i - e * XCH;
                int tg = t + c;
                s->xbuf[e][c] = (tg < T) ? x[(size_t)(base + e) * T + tg] : 0.f;
            }
            __syncthreads();
        }
        const int xidx = t % XCH;
        const int nxt = cur ^ 1;

        // -------- output linear for step t-1 --------
        if (t > 0 && tid < E) {
            const ulonglong2* hv = (const ulonglong2*)&s->h2[cur][tid][0];
            const ulonglong2* wl = (const ulonglong2*)s->wlin;
            ull acc = pack2(s->blin, 0.f);
            #pragma unroll
            for (int k = 0; k < KU2; k++) {
                ulonglong2 h = hv[k], w = wl[k];
                fma2(acc, h.x, w.x); fma2(acc, h.y, w.y);
            }
            float o = sum2(acc);
            out[(size_t)(base + tid) * TF + (t - 1)] = o;
            s->outp[tid] = o;
        }
        if (t >= T) __syncthreads();   // phase 2: outp feeds L1

        // ================= layer 1: tile 2j x 4e, k-half =================
        {
            ull aR[2][4], aZ[2][4], aN[2][4];
            #pragma unroll
            for (int jj = 0; jj < 2; jj++)
                #pragma unroll
                for (int ei = 0; ei < 4; ei++) {
                    aR[jj][ei] = (kh == 0) ? pack2(s->bR1[j0 + jj], 0.f) : 0ull;
                    aZ[jj][ei] = (kh == 0) ? pack2(s->bZ1[j0 + jj], 0.f) : 0ull;
                    aN[jj][ei] = (kh == 0) ? pack2(s->bHN1[j0 + jj], 0.f) : 0ull;
                }
            const ulonglong2* pr = (const ulonglong2*)&s->l1r[jg * PAIR] + kb;
            const ulonglong2* pz = (const ulonglong2*)&s->l1z[jg * PAIR] + kb;
            const ulonglong2* pn = (const ulonglong2*)&s->l1n[jg * PAIR] + kb;
            const ulonglong2* ph = (const ulonglong2*)&s->h1[cur][0][0] + eg * KU2 + kb;
            #pragma unroll
            for (int ki = 0; ki < 7; ki++) {
                ulonglong2 w[6];
                w[0] = pr[ki]; w[1] = pr[ki + KU2];
                w[2] = pz[ki]; w[3] = pz[ki + KU2];
                w[4] = pn[ki]; w[5] = pn[ki + KU2];
                ulonglong2 hv[4];
                #pragma unroll
                for (int ei = 0; ei < 4; ei++) hv[ei] = ph[ki + ei * 4 * KU2];
                #pragma unroll
                for (int jj = 0; jj < 2; jj++)
                    #pragma unroll
                    for (int ei = 0; ei < 4; ei++) {
                        fma2(aR[jj][ei], hv[ei].x, w[0 + jj].x); fma2(aR[jj][ei], hv[ei].y, w[0 + jj].y);
                        fma2(aZ[jj][ei], hv[ei].x, w[2 + jj].x); fma2(aZ[jj][ei], hv[ei].y, w[2 + jj].y);
                        fma2(aN[jj][ei], hv[ei].x, w[4 + jj].x); fma2(aN[jj][ei], hv[ei].y, w[4 + jj].y);
                    }
            }
            // exchange partials: this lane finalizes row jme = j0 + kh only
            float gr[4], gz[4], gn[4];
            #pragma unroll
            for (int ei = 0; ei < 4; ei++) {
                gr[ei] = xred(aR[0][ei], aR[1][ei], kh);
                gz[ei] = xred(aZ[0][ei], aZ[1][ei], kh);
                gn[ei] = xred(aN[0][ei], aN[1][ei], kh);
            }
            const float wr1 = s->wih1r[jme], wz1 = s->wih1z[jme];
            const float wn1 = s->wih1n[jme], bi  = s->bIN1[jme];
            #pragma unroll
            for (int ei = 0; ei < 4; ei++) {
                int el = eg + 4 * ei;
                float xv = (t < T) ? s->xbuf[el][xidx] : s->outp[el];
                float ho = s->h1[cur][el][jme];
                float nh = gru_cell(fmaf(xv, wr1, gr[ei]), fmaf(xv, wz1, gz[ei]),
                                    fmaf(xv, wn1, bi), gn[ei], ho);
                s->h1[nxt][el][jme] = nh;
            }
        }
        __syncthreads();

        // ================= layer 2: tile 2j x 4e, k-half =================
        {
            ull aR[2][4], aZ[2][4], aI[2][4], aH[2][4];
            #pragma unroll
            for (int jj = 0; jj < 2; jj++)
                #pragma unroll
                for (int ei = 0; ei < 4; ei++) {
                    aR[jj][ei] = (kh == 0) ? pack2(s->bR2[j0 + jj], 0.f) : 0ull;
                    aZ[jj][ei] = (kh == 0) ? pack2(s->bZ2[j0 + jj], 0.f) : 0ull;
                    aI[jj][ei] = (kh == 0) ? pack2(s->bIN2[j0 + jj], 0.f) : 0ull;
                    aH[jj][ei] = (kh == 0) ? pack2(s->bHN2[j0 + jj], 0.f) : 0ull;
                }
            const ulonglong2* pir = (const ulonglong2*)&s->ir2[jg * PAIR] + kb;
            const ulonglong2* piz = (const ulonglong2*)&s->iz2[jg * PAIR] + kb;
            const ulonglong2* pin = (const ulonglong2*)&s->in2[jg * PAIR] + kb;
            const ulonglong2* phr = (const ulonglong2*)&s->hr2[jg * PAIR] + kb;
            const ulonglong2* phz = (const ulonglong2*)&s->hz2[jg * PAIR] + kb;
            const ulonglong2* phn = (const ulonglong2*)&s->hn2[jg * PAIR] + kb;
            const ulonglong2* pu  = (const ulonglong2*)&s->h1[nxt][0][0] + eg * KU2 + kb;
            const ulonglong2* pv  = (const ulonglong2*)&s->h2[cur][0][0] + eg * KU2 + kb;
            #pragma unroll
            for (int ki = 0; ki < 7; ki++) {
                ulonglong2 wi[6], wh[6];
                wi[0] = pir[ki]; wi[1] = pir[ki + KU2];
                wi[2] = piz[ki]; wi[3] = piz[ki + KU2];
                wi[4] = pin[ki]; wi[5] = pin[ki + KU2];
                wh[0] = phr[ki]; wh[1] = phr[ki + KU2];
                wh[2] = phz[ki]; wh[3] = phz[ki + KU2];
                wh[4] = phn[ki]; wh[5] = phn[ki + KU2];
                ulonglong2 uv[4], vv[4];
                #pragma unroll
                for (int ei = 0; ei < 4; ei++) {
                    uv[ei] = pu[ki + ei * 4 * KU2];
                    vv[ei] = pv[ki + ei * 4 * KU2];
                }
                #pragma unroll
                for (int jj = 0; jj < 2; jj++)
                    #pragma unroll
                    for (int ei = 0; ei < 4; ei++) {
                        fma2(aR[jj][ei], uv[ei].x, wi[0 + jj].x); fma2(aR[jj][ei], uv[ei].y, wi[0 + jj].y);
                        fma2(aR[jj][ei], vv[ei].x, wh[0 + jj].x); fma2(aR[jj][ei], vv[ei].y, wh[0 + jj].y);
                        fma2(aZ[jj][ei], uv[ei].x, wi[2 + jj].x); fma2(aZ[jj][ei], uv[ei].y, wi[2 + jj].y);
                        fma2(aZ[jj][ei], vv[ei].x, wh[2 + jj].x); fma2(aZ[jj][ei], vv[ei].y, wh[2 + jj].y);
                        fma2(aI[jj][ei], uv[ei].x, wi[4 + jj].x); fma2(aI[jj][ei], uv[ei].y, wi[4 + jj].y);
                        fma2(aH[jj][ei], vv[ei].x, wh[4 + jj].x); fma2(aH[jj][ei], vv[ei].y, wh[4 + jj].y);
                    }
            }
            float gr[4], gz[4], gi[4], gh[4];
            #pragma unroll
            for (int ei = 0; ei < 4; ei++) {
                gr[ei] = xred(aR[0][ei], aR[1][ei], kh);
                gz[ei] = xred(aZ[0][ei], aZ[1][ei], kh);
                gi[ei] = xred(aI[0][ei], aI[1][ei], kh);
                gh[ei] = xred(aH[0][ei], aH[1][ei], kh);
            }
            #pragma unroll
            for (int ei = 0; ei < 4; ei++) {
                int el = eg + 4 * ei;
                float ho = s->h2[cur][el][jme];
                float nh = gru_cell(gr[ei], gz[ei], gi[ei], gh[ei], ho);
                s->h2[nxt][el][jme] = nh;
            }
        }
        __syncthreads();

        cur = nxt;
    }

    // final output (step TF-1)
    if (tid < E) {
        const ulonglong2* hv = (const ulonglong2*)&s->h2[cur][tid][0];
        const ulonglong2* wl = (const ulonglong2*)s->wlin;
        ull acc = pack2(s->blin, 0.f);
        #pragma unroll
        for (int k = 0; k < KU2; k++) {
            ulonglong2 h = hv[k], w = wl[k];
            fma2(acc, h.x, w.x); fma2(acc, h.y, w.y);
        }
        out[(size_t)(base + tid) * TF + (TF - 1)] = sum2(acc);
    }
}

extern "C" void kernel_launch(void* const* d_in, const int* in_sizes, int n_in,
                              void* d_out, int out_size)
{
    const float* x     = (const float*)d_in[0];
    const float* w_ih1 = (const float*)d_in[1];
    const float* w_hh1 = (const float*)d_in[2];
    const float* b_ih1 = (const float*)d_in[3];
    const float* b_hh1 = (const float*)d_in[4];
    const float* w_ih2 = (const float*)d_in[5];
    const float* w_hh2 = (const float*)d_in[6];
    const float* b_ih2 = (const float*)d_in[7];
    const float* b_hh2 = (const float*)d_in[8];
    const float* w_lin = (const float*)d_in[9];
    const float* b_lin = (const float*)d_in[10];

    const int B  = B_TOT;
    const int T  = in_sizes[0] / B;
    const int TF = out_size / B;
    const int F  = TF - T;

    size_t shmem = sizeof(Smem);
    cudaFuncSetAttribute(gru_stack_kernel,
                         cudaFuncAttributeMaxDynamicSharedMemorySize, (int)shmem);

    gru_stack_kernel<<<B / E, TPB, shmem>>>(
        x, w_ih1, w_hh1, b_ih1, b_hh1,
        w_ih2, w_hh2, b_ih2, b_hh2,
        w_lin, b_lin, (float*)d_out, T, F);
}